// round 12
// baseline (speedup 1.0000x reference)
#include <cuda_runtime.h>
#include <cstdint>

#define B_ 32
#define S_ 128
#define E_ 512
#define F_ 2048

#define KC   16             // K chunk (both kernels)
#define AST  20             // A smem row stride for 16-float rows (conflict-free frags)

// ---- gemm1: CTA 256 thr, M=32 x N=256, K=512, 4-stage ----
#define NT1   256
#define NKC1  32
#define BST1  264
#define ASZ1  (32 * AST)          // 640
#define BSZ1  (KC * BST1)         // 4224
#define STG1  (ASZ1 + BSZ1)       // 4864 floats
#define NSTG1 4
#define SMEM1 (NSTG1 * STG1 * 4)  // 77824 B
#define YST1  260

// ---- gemm2 fused: CTA 512 thr, M=32 x N=512, K=2048, 6-stage ----
#define NKC2  128
#define BST2  520
#define ASZ2  (32 * AST)          // 640
#define BSZ2  (KC * BST2)         // 8320
#define STG2  (ASZ2 + BSZ2)       // 8960 floats
#define NSTG2 6
#define SMEM2 (NSTG2 * STG2 * 4)  // 215040 B

// Scratch (device global: allocation-free)
__device__ float g_H[(size_t)S_ * B_ * F_];   // H[s][b][f]

__device__ __forceinline__ float to_tf32(float x) {
    float r; asm("cvt.rna.tf32.f32 %0, %1;" : "=f"(r) : "f"(x)); return r;
}
__device__ __forceinline__ uint32_t frag(const float* p) {
    return __float_as_uint(to_tf32(*p));
}
__device__ __forceinline__ uint32_t smem_u32(const void* p) {
    uint32_t a;
    asm("{ .reg .u64 t; cvta.to.shared.u64 t, %1; cvt.u32.u64 %0, t; }"
        : "=r"(a) : "l"(p));
    return a;
}
__device__ __forceinline__ void cp16(uint32_t s, const void* g) {
    asm volatile("cp.async.cg.shared.global [%0], [%1], 16;"
                 :: "r"(s), "l"(g) : "memory");
}
#define CP_COMMIT() asm volatile("cp.async.commit_group;" ::: "memory")
#define CP_WAITN(n) asm volatile("cp.async.wait_group %0;" :: "n"(n) : "memory")

#define MMA_TF32(ac, a, b)                                                  \
    asm volatile(                                                           \
        "mma.sync.aligned.m16n8k8.row.col.f32.tf32.tf32.f32 "               \
        "{%0,%1,%2,%3}, {%4,%5,%6,%7}, {%8,%9}, {%0,%1,%2,%3};"             \
        : "+f"((ac)[0]), "+f"((ac)[1]), "+f"((ac)[2]), "+f"((ac)[3])        \
        : "r"((a)[0]), "r"((a)[1]), "r"((a)[2]), "r"((a)[3]),               \
          "r"((b)[0]), "r"((b)[1]))

// ---------------------------------------------------------------------------
// GEMM1: H[s][b][f] = sum_e x[b][s][e]*W1[s][e][f] + b1[s][f]
// grid (F/256, S), 256 thr, 4-stage cp.async (3 in flight), KC=16.
// ---------------------------------------------------------------------------
__global__ __launch_bounds__(256, 2)
void gemm1_kernel(const float* __restrict__ X, const float* __restrict__ W,
                  const float* __restrict__ bias)
{
    extern __shared__ float sm[];
    const uint32_t smb = smem_u32(sm);
    const int tid  = threadIdx.x;
    const int warp = tid >> 5, lane = tid & 31;
    const int g = lane >> 2, t = lane & 3;
    const int wn = warp * 32;
    const int s  = blockIdx.y;
    const int n0 = blockIdx.x * NT1;

    const float* Arow = X + (size_t)s * E_;           const size_t lda = (size_t)S_ * E_;
    const float* Bb   = W + (size_t)s * E_ * F_ + n0; const size_t ldb = F_;
    float* Cb = g_H + (size_t)s * B_ * F_ + n0;       const size_t ldc = F_;
    const float* bi = bias + (size_t)s * F_ + n0;

    // producers: A (tid<128): 32 rows x 4 f4 per row; B (all): 4 f4 each
    const int am = tid >> 2, akf = tid & 3;
    const float* Aload = Arow + (size_t)am * lda + akf * 4;
    const uint32_t asts = smb + (am * AST + akf * 4) * 4;
    int bgo[4]; uint32_t bsts[4];
#pragma unroll
    for (int r = 0; r < 4; r++) {
        const int idx = r * 256 + tid;                 // 0..1023
        const int bk = idx >> 6, bn = (idx & 63) * 4;  // 16 k-rows x 64 f4
        bgo[r]  = bk * (int)ldb + bn;
        bsts[r] = smb + (ASZ1 + bk * BST1 + bn) * 4;
    }

    auto issue = [&](int kc) {
        const uint32_t off = (uint32_t)(kc & (NSTG1 - 1)) * (STG1 * 4);
        if (tid < 128) cp16(asts + off, Aload + kc * KC);
        const float* bp = Bb + (size_t)kc * KC * ldb;
#pragma unroll
        for (int r = 0; r < 4; r++) cp16(bsts[r] + off, bp + bgo[r]);
        CP_COMMIT();
    };

    float acc[2][4][4];
#pragma unroll
    for (int i = 0; i < 2; i++)
#pragma unroll
        for (int j = 0; j < 4; j++)
#pragma unroll
            for (int c = 0; c < 4; c++) acc[i][j][c] = 0.0f;

    issue(0); issue(1); issue(2);
    for (int kc = 0; kc < NKC1; kc++) {
        if      (kc + 3 < NKC1) CP_WAITN(2);
        else if (kc + 2 < NKC1) CP_WAITN(1);
        else                    CP_WAITN(0);
        __syncthreads();
        if (kc + 3 < NKC1) issue(kc + 3);

        const float* As = sm + (kc & (NSTG1 - 1)) * STG1;
        const float* Bs = As + ASZ1;
#pragma unroll
        for (int ks = 0; ks < 2; ks++) {
            const int kb = ks * 8;
            uint32_t af[2][4], bf[4][2];
#pragma unroll
            for (int i = 0; i < 2; i++) {
                af[i][0] = frag(&As[(16 * i + g)     * AST + kb + t]);
                af[i][1] = frag(&As[(16 * i + 8 + g) * AST + kb + t]);
                af[i][2] = frag(&As[(16 * i + g)     * AST + kb + t + 4]);
                af[i][3] = frag(&As[(16 * i + 8 + g) * AST + kb + t + 4]);
            }
#pragma unroll
            for (int j = 0; j < 4; j++) {
                bf[j][0] = frag(&Bs[(kb + t)     * BST1 + wn + 8 * j + g]);
                bf[j][1] = frag(&Bs[(kb + t + 4) * BST1 + wn + 8 * j + g]);
            }
#pragma unroll
            for (int i = 0; i < 2; i++)
#pragma unroll
                for (int j = 0; j < 4; j++) MMA_TF32(acc[i][j], af[i], bf[j]);
        }
    }
    __syncthreads();   // all warps done before smem reuse

    float* Yb = sm;
#pragma unroll
    for (int i = 0; i < 2; i++)
#pragma unroll
        for (int j = 0; j < 4; j++) {
            const int m0 = 16 * i + g, n = wn + 8 * j + 2 * t;
            Yb[m0 * YST1 + n]           = acc[i][j][0];
            Yb[m0 * YST1 + n + 1]       = acc[i][j][1];
            Yb[(m0 + 8) * YST1 + n]     = acc[i][j][2];
            Yb[(m0 + 8) * YST1 + n + 1] = acc[i][j][3];
        }
    __syncthreads();
#pragma unroll
    for (int r = 0; r < 8; r++) {
        const int idx = r * 256 + tid;
        const int m = idx >> 6, nf = (idx & 63) * 4;
        float4 v = *(const float4*)&Yb[m * YST1 + nf];
        const float4 bb = *(const float4*)(bi + nf);
        v.x += bb.x; v.y += bb.y; v.z += bb.z; v.w += bb.w;
        *(float4*)(Cb + (size_t)m * ldc + nf) = v;
    }
}

// ---------------------------------------------------------------------------
// GEMM2 fused: out[b][s][:] = LN( H[s][b][:] @ W2[s] + b2[s] + x[b][s][:] )
// grid (S) = 128 CTAs, 512 thr / 16 warps. M=32 x N=512, K=2048,
// 6-stage cp.async (5 in flight), KC=16, LN fused in epilogue.
// ---------------------------------------------------------------------------
__global__ __launch_bounds__(512, 1)
void gemm2_fused(const float* __restrict__ x, const float* __restrict__ W2,
                 const float* __restrict__ b2, const float* __restrict__ gamma,
                 const float* __restrict__ beta, float* __restrict__ out)
{
    extern __shared__ float sm[];
    const uint32_t smb = smem_u32(sm);
    const int tid  = threadIdx.x;
    const int warp = tid >> 5, lane = tid & 31;
    const int g = lane >> 2, t = lane & 3;
    const int wn = warp * 32;
    const int s = blockIdx.x;

    const float* Arow = g_H + (size_t)s * B_ * F_;   // lda = F_
    const float* Bb   = W2 + (size_t)s * F_ * E_;    // ldb = E_

    // producers: A (tid<128): 32 rows x 4 f4 per row; B (all 512): 4 f4 each
    const int am = tid >> 2, akf = tid & 3;
    const float* Aload = Arow + (size_t)am * F_ + akf * 4;
    const uint32_t asts = smb + (am * AST + akf * 4) * 4;
    int bgo[4]; uint32_t bsts[4];
#pragma unroll
    for (int r = 0; r < 4; r++) {
        const int idx = r * 512 + tid;                  // 0..2047
        const int bk = idx >> 7, bn = (idx & 127) * 4;  // 16 k-rows x 128 f4
        bgo[r]  = bk * E_ + bn;
        bsts[r] = smb + (ASZ2 + bk * BST2 + bn) * 4;
    }

    auto issue = [&](int kc) {
        const uint32_t off = (uint32_t)(kc % NSTG2) * (STG2 * 4);
        if (tid < 128) cp16(asts + off, Aload + kc * KC);
        const float* bp = Bb + (size_t)kc * KC * E_;
#pragma unroll
        for (int r = 0; r < 4; r++) cp16(bsts[r] + off, bp + bgo[r]);
        CP_COMMIT();
    };

    float acc[2][4][4];
#pragma unroll
    for (int i = 0; i < 2; i++)
#pragma unroll
        for (int j = 0; j < 4; j++)
#pragma unroll
            for (int c = 0; c < 4; c++) acc[i][j][c] = 0.0f;

    issue(0); issue(1); issue(2); issue(3); issue(4);
    for (int kc = 0; kc < NKC2; kc++) {
        if      (kc + 5 < NKC2) CP_WAITN(4);
        else if (kc + 4 < NKC2) CP_WAITN(3);
        else if (kc + 3 < NKC2) CP_WAITN(2);
        else if (kc + 2 < NKC2) CP_WAITN(1);
        else                    CP_WAITN(0);
        __syncthreads();
        if (kc + 5 < NKC2) issue(kc + 5);

        const float* As = sm + (kc % NSTG2) * STG2;
        const float* Bs = As + ASZ2;
#pragma unroll
        for (int ks = 0; ks < 2; ks++) {
            const int kb = ks * 8;
            uint32_t af[2][4], bf[4][2];
#pragma unroll
            for (int i = 0; i < 2; i++) {
                af[i][0] = frag(&As[(16 * i + g)     * AST + kb + t]);
                af[i][1] = frag(&As[(16 * i + 8 + g) * AST + kb + t]);
                af[i][2] = frag(&As[(16 * i + g)     * AST + kb + t + 4]);
                af[i][3] = frag(&As[(16 * i + 8 + g) * AST + kb + t + 4]);
            }
#pragma unroll
            for (int j = 0; j < 4; j++) {
                bf[j][0] = frag(&Bs[(kb + t)     * BST2 + wn + 8 * j + g]);
                bf[j][1] = frag(&Bs[(kb + t + 4) * BST2 + wn + 8 * j + g]);
            }
#pragma unroll
            for (int i = 0; i < 2; i++)
#pragma unroll
                for (int j = 0; j < 4; j++) MMA_TF32(acc[i][j], af[i], bf[j]);
        }
    }
    __syncthreads();   // all warps done before smem reuse

    // ---- Epilogue: transpose to smem, then per-row LayerNorm ----
    float* Yb = sm;    // 32 x BST2 floats = 66.6 KB
#pragma unroll
    for (int i = 0; i < 2; i++)
#pragma unroll
        for (int j = 0; j < 4; j++) {
            const int m0 = 16 * i + g, n = wn + 8 * j + 2 * t;
            Yb[m0 * BST2 + n]           = acc[i][j][0];
            Yb[m0 * BST2 + n + 1]       = acc[i][j][1];
            Yb[(m0 + 8) * BST2 + n]     = acc[i][j][2];
            Yb[(m0 + 8) * BST2 + n + 1] = acc[i][j][3];
        }
    __syncthreads();

    // warp w handles batch rows 2w and 2w+1; lane covers e = lane + 32*i
#pragma unroll
    for (int rr = 0; rr < 2; rr++) {
        const int m = warp * 2 + rr;
        const float* xr = x + ((size_t)m * S_ + s) * E_;
        const float* bb = b2 + (size_t)s * E_;
        float v[16];
        float sum = 0.0f, sq = 0.0f;
#pragma unroll
        for (int i = 0; i < 16; i++) {
            const int e = lane + 32 * i;
            const float y = Yb[m * BST2 + e] + bb[e] + xr[e];
            v[i] = y;
            sum += y; sq += y * y;
        }
#pragma unroll
        for (int o = 16; o > 0; o >>= 1) {
            sum += __shfl_xor_sync(0xFFFFFFFFu, sum, o);
            sq  += __shfl_xor_sync(0xFFFFFFFFu, sq, o);
        }
        const float mu  = sum * (1.0f / E_);
        const float var = sq * (1.0f / E_) - mu * mu;
        const float inv = rsqrtf(var + 1e-5f);
        float* orow = out + ((size_t)m * S_ + s) * E_;
#pragma unroll
        for (int i = 0; i < 16; i++) {
            const int e = lane + 32 * i;
            orow[e] = (v[i] - mu) * inv * gamma[e] + beta[e];
        }
    }
}

// ---------------------------------------------------------------------------
extern "C" void kernel_launch(void* const* d_in, const int* in_sizes, int n_in,
                              void* d_out, int out_size)
{
    const float* x     = (const float*)d_in[0];
    const float* W1    = (const float*)d_in[1];
    const float* b1    = (const float*)d_in[2];
    const float* W2    = (const float*)d_in[3];
    const float* b2    = (const float*)d_in[4];
    const float* gamma = (const float*)d_in[5];
    const float* beta  = (const float*)d_in[6];
    float* out = (float*)d_out;

    // Idempotent, host-side only, not a stream op: safe on every call.
    cudaFuncSetAttribute(gemm1_kernel,
                         cudaFuncAttributeMaxDynamicSharedMemorySize, SMEM1);
    cudaFuncSetAttribute(gemm2_fused,
                         cudaFuncAttributeMaxDynamicSharedMemorySize, SMEM2);

    gemm1_kernel<<<dim3(F_ / NT1, S_), 256, SMEM1>>>(x, W1, b1);
    gemm2_fused<<<S_, 512, SMEM2>>>(x, W2, b2, gamma, beta, out);
}

// round 14
// speedup vs baseline: 1.4548x; 1.4548x over previous
#include <cuda_runtime.h>
#include <cstdint>

#define B_ 32
#define S_ 128
#define E_ 512
#define F_ 2048

#define KC   32             // K chunk (both kernels)
#define AST  36             // A smem row stride (floats), conflict-free frags

// ---- gemm1: CTA 256 thr, M=32 x N=256, K=512, 2-stage (proven R8) ----
#define NT1  256
#define NKC1 16
#define BST1 264
#define ASZ1 (32 * AST)          // 1152
#define BSZ1 (KC * BST1)         // 8448
#define STG1 (ASZ1 + BSZ1)       // 9600 floats
#define SMEM1 (2 * STG1 * 4)     // 76800 B
#define YST1 260

// ---- gemm2 fused: CTA 512 thr, M=32 x N=512, K=2048, 3-stage (proven R9) ----
#define NKC2 64
#define BST2 520
#define ASZ2 (32 * AST)          // 1152
#define BSZ2 (KC * BST2)         // 16640
#define STG2 (ASZ2 + BSZ2)       // 17792 floats
#define SMEM2 (3 * STG2 * 4)     // 213504 B

// Scratch (device global: allocation-free)
__device__ float g_H[(size_t)S_ * B_ * F_];   // H[s][b][f]

__device__ __forceinline__ float to_tf32(float x) {
    float r; asm("cvt.rna.tf32.f32 %0, %1;" : "=f"(r) : "f"(x)); return r;
}
__device__ __forceinline__ uint32_t frag(const float* p) {
    return __float_as_uint(to_tf32(*p));
}
__device__ __forceinline__ uint32_t smem_u32(const void* p) {
    uint32_t a;
    asm("{ .reg .u64 t; cvta.to.shared.u64 t, %1; cvt.u32.u64 %0, t; }"
        : "=r"(a) : "l"(p));
    return a;
}
__device__ __forceinline__ void cp16(uint32_t s, const void* g) {
    asm volatile("cp.async.cg.shared.global [%0], [%1], 16;"
                 :: "r"(s), "l"(g) : "memory");
}
#define CP_COMMIT() asm volatile("cp.async.commit_group;" ::: "memory")
#define CP_WAIT1()  asm volatile("cp.async.wait_group 1;" ::: "memory")
#define CP_WAIT0()  asm volatile("cp.async.wait_group 0;" ::: "memory")

#define MMA_TF32(ac, a, b)                                                  \
    asm volatile(                                                           \
        "mma.sync.aligned.m16n8k8.row.col.f32.tf32.tf32.f32 "               \
        "{%0,%1,%2,%3}, {%4,%5,%6,%7}, {%8,%9}, {%0,%1,%2,%3};"             \
        : "+f"((ac)[0]), "+f"((ac)[1]), "+f"((ac)[2]), "+f"((ac)[3])        \
        : "r"((a)[0]), "r"((a)[1]), "r"((a)[2]), "r"((a)[3]),               \
          "r"((b)[0]), "r"((b)[1]))

// ---------------------------------------------------------------------------
// GEMM1 (exact R8 structure): H[s][b][f] = sum_e x[b][s][e]*W1[s][e][f] + b1
// grid (F/256, S), 256 thr, 2-stage cp.async, KC=32.
// ---------------------------------------------------------------------------
__global__ __launch_bounds__(256, 2)
void gemm1_kernel(const float* __restrict__ X, const float* __restrict__ W,
                  const float* __restrict__ bias)
{
    extern __shared__ float sm[];
    const uint32_t smb = smem_u32(sm);
    const int tid  = threadIdx.x;
    const int warp = tid >> 5, lane = tid & 31;
    const int g = lane >> 2, t = lane & 3;
    const int wn = warp * 32;
    const int s  = blockIdx.y;
    const int n0 = blockIdx.x * NT1;

    const float* Arow = X + (size_t)s * E_;           const size_t lda = (size_t)S_ * E_;
    const float* Bb   = W + (size_t)s * E_ * F_ + n0; const size_t ldb = F_;
    float* Cb = g_H + (size_t)s * B_ * F_ + n0;       const size_t ldc = F_;
    const float* bi = bias + (size_t)s * F_ + n0;

    const int am = tid >> 3, akf = tid & 7;           // A: 32 rows x 8 f4
    const float* Aload = Arow + (size_t)am * lda + akf * 4;
    const uint32_t asts = smb + (am * AST + akf * 4) * 4;
    int bgo[8]; uint32_t bsts[8];
#pragma unroll
    for (int r = 0; r < 8; r++) {
        const int idx = r * 256 + tid;
        const int bk = idx >> 6, bn = (idx & 63) * 4; // 32 k-rows x 64 f4
        bgo[r]  = bk * (int)ldb + bn;
        bsts[r] = smb + (ASZ1 + bk * BST1 + bn) * 4;
    }

    auto issue = [&](int kc) {
        const uint32_t off = (kc & 1) * (STG1 * 4);
        cp16(asts + off, Aload + kc * KC);
        const float* bp = Bb + (size_t)kc * KC * ldb;
#pragma unroll
        for (int r = 0; r < 8; r++) cp16(bsts[r] + off, bp + bgo[r]);
        CP_COMMIT();
    };

    float acc[2][4][4];
#pragma unroll
    for (int i = 0; i < 2; i++)
#pragma unroll
        for (int j = 0; j < 4; j++)
#pragma unroll
            for (int c = 0; c < 4; c++) acc[i][j][c] = 0.0f;

    issue(0);
    for (int kc = 0; kc < NKC1; kc++) {
        if (kc + 1 < NKC1) { issue(kc + 1); CP_WAIT1(); }
        else               { CP_WAIT0(); }
        __syncthreads();
        const float* As = sm + (kc & 1) * STG1;
        const float* Bs = As + ASZ1;
#pragma unroll
        for (int ks = 0; ks < 4; ks++) {
            const int kb = ks * 8;
            uint32_t af[2][4], bf[4][2];
#pragma unroll
            for (int i = 0; i < 2; i++) {
                af[i][0] = frag(&As[(16 * i + g)     * AST + kb + t]);
                af[i][1] = frag(&As[(16 * i + 8 + g) * AST + kb + t]);
                af[i][2] = frag(&As[(16 * i + g)     * AST + kb + t + 4]);
                af[i][3] = frag(&As[(16 * i + 8 + g) * AST + kb + t + 4]);
            }
#pragma unroll
            for (int j = 0; j < 4; j++) {
                bf[j][0] = frag(&Bs[(kb + t)     * BST1 + wn + 8 * j + g]);
                bf[j][1] = frag(&Bs[(kb + t + 4) * BST1 + wn + 8 * j + g]);
            }
#pragma unroll
            for (int i = 0; i < 2; i++)
#pragma unroll
                for (int j = 0; j < 4; j++) MMA_TF32(acc[i][j], af[i], bf[j]);
        }
        __syncthreads();   // stage (kc&1) free for chunk kc+2
    }

    float* Yb = sm;
#pragma unroll
    for (int i = 0; i < 2; i++)
#pragma unroll
        for (int j = 0; j < 4; j++) {
            const int m0 = 16 * i + g, n = wn + 8 * j + 2 * t;
            Yb[m0 * YST1 + n]           = acc[i][j][0];
            Yb[m0 * YST1 + n + 1]       = acc[i][j][1];
            Yb[(m0 + 8) * YST1 + n]     = acc[i][j][2];
            Yb[(m0 + 8) * YST1 + n + 1] = acc[i][j][3];
        }
    __syncthreads();
#pragma unroll
    for (int r = 0; r < 8; r++) {
        const int idx = r * 256 + tid;
        const int m = idx >> 6, nf = (idx & 63) * 4;
        float4 v = *(const float4*)&Yb[m * YST1 + nf];
        const float4 bb = *(const float4*)(bi + nf);
        v.x += bb.x; v.y += bb.y; v.z += bb.z; v.w += bb.w;
        *(float4*)(Cb + (size_t)m * ldc + nf) = v;
    }
}

// ---------------------------------------------------------------------------
// GEMM2 fused (R9 + single barrier/chunk):
// out[b][s][:] = LN( H[s][b][:] @ W2[s] + b2[s] + x[b][s][:] )
// grid (S) = 128 CTAs, 512 thr. M=32 x N=512, K=2048, 3-stage, KC=32.
// ---------------------------------------------------------------------------
__global__ __launch_bounds__(512, 1)
void gemm2_fused(const float* __restrict__ x, const float* __restrict__ W2,
                 const float* __restrict__ b2, const float* __restrict__ gamma,
                 const float* __restrict__ beta, float* __restrict__ out)
{
    extern __shared__ float sm[];
    const uint32_t smb = smem_u32(sm);
    const int tid  = threadIdx.x;
    const int warp = tid >> 5, lane = tid & 31;
    const int g = lane >> 2, t = lane & 3;
    const int wn = warp * 32;
    const int s = blockIdx.x;

    const float* Arow = g_H + (size_t)s * B_ * F_;   // lda = F_
    const float* Bb   = W2 + (size_t)s * F_ * E_;    // ldb = E_

    const int am = tid >> 3, akf = tid & 7;          // A by tid<256
    const float* Aload = Arow + (size_t)am * F_ + akf * 4;
    const uint32_t asts = smb + (am * AST + akf * 4) * 4;
    int bgo[8]; uint32_t bsts[8];
#pragma unroll
    for (int r = 0; r < 8; r++) {
        const int idx = r * 512 + tid;                 // 0..4095
        const int bk = idx >> 7, bn = (idx & 127) * 4; // 32 k-rows x 128 f4
        bgo[r]  = bk * E_ + bn;
        bsts[r] = smb + (ASZ2 + bk * BST2 + bn) * 4;
    }

    auto issue = [&](int kc) {
        const uint32_t off = (uint32_t)(kc % 3) * (STG2 * 4);
        if (tid < 256) cp16(asts + off, Aload + kc * KC);
        const float* bp = Bb + (size_t)kc * KC * E_;
#pragma unroll
        for (int r = 0; r < 8; r++) cp16(bsts[r] + off, bp + bgo[r]);
        CP_COMMIT();
    };

    float acc[2][4][4];
#pragma unroll
    for (int i = 0; i < 2; i++)
#pragma unroll
        for (int j = 0; j < 4; j++)
#pragma unroll
            for (int c = 0; c < 4; c++) acc[i][j][c] = 0.0f;

    issue(0);
    issue(1);
    for (int kc = 0; kc < NKC2; kc++) {
        if (kc + 1 < NKC2) CP_WAIT1(); else CP_WAIT0();
        __syncthreads();
        // stage (kc+2)%3 == (kc-1)%3: consumed before this barrier -> safe
        if (kc + 2 < NKC2) issue(kc + 2);

        const float* As = sm + (kc % 3) * STG2;
        const float* Bs = As + ASZ2;
#pragma unroll
        for (int ks = 0; ks < 4; ks++) {
            const int kb = ks * 8;
            uint32_t af[2][4], bf[4][2];
#pragma unroll
            for (int i = 0; i < 2; i++) {
                af[i][0] = frag(&As[(16 * i + g)     * AST + kb + t]);
                af[i][1] = frag(&As[(16 * i + 8 + g) * AST + kb + t]);
                af[i][2] = frag(&As[(16 * i + g)     * AST + kb + t + 4]);
                af[i][3] = frag(&As[(16 * i + 8 + g) * AST + kb + t + 4]);
            }
#pragma unroll
            for (int j = 0; j < 4; j++) {
                bf[j][0] = frag(&Bs[(kb + t)     * BST2 + wn + 8 * j + g]);
                bf[j][1] = frag(&Bs[(kb + t + 4) * BST2 + wn + 8 * j + g]);
            }
#pragma unroll
            for (int i = 0; i < 2; i++)
#pragma unroll
                for (int j = 0; j < 4; j++) MMA_TF32(acc[i][j], af[i], bf[j]);
        }
    }
    __syncthreads();   // all warps done before smem reuse

    // ---- Epilogue: transpose to smem, then per-row LayerNorm ----
    float* Yb = sm;    // 32 x BST2 floats = 66.6 KB
#pragma unroll
    for (int i = 0; i < 2; i++)
#pragma unroll
        for (int j = 0; j < 4; j++) {
            const int m0 = 16 * i + g, n = wn + 8 * j + 2 * t;
            Yb[m0 * BST2 + n]           = acc[i][j][0];
            Yb[m0 * BST2 + n + 1]       = acc[i][j][1];
            Yb[(m0 + 8) * BST2 + n]     = acc[i][j][2];
            Yb[(m0 + 8) * BST2 + n + 1] = acc[i][j][3];
        }
    __syncthreads();

    // warp w handles batch rows 2w, 2w+1; lane covers e = lane + 32*i
#pragma unroll
    for (int rr = 0; rr < 2; rr++) {
        const int m = warp * 2 + rr;
        const float* xr = x + ((size_t)m * S_ + s) * E_;
        const float* bb = b2 + (size_t)s * E_;
        float v[16];
        float sum = 0.0f, sq = 0.0f;
#pragma unroll
        for (int i = 0; i < 16; i++) {
            const int e = lane + 32 * i;
            const float y = Yb[m * BST2 + e] + bb[e] + xr[e];
            v[i] = y;
            sum += y; sq += y * y;
        }
#pragma unroll
        for (int o = 16; o > 0; o >>= 1) {
            sum += __shfl_xor_sync(0xFFFFFFFFu, sum, o);
            sq  += __shfl_xor_sync(0xFFFFFFFFu, sq, o);
        }
        const float mu  = sum * (1.0f / E_);
        const float var = sq * (1.0f / E_) - mu * mu;
        const float inv = rsqrtf(var + 1e-5f);
        float* orow = out + ((size_t)m * S_ + s) * E_;
#pragma unroll
        for (int i = 0; i < 16; i++) {
            const int e = lane + 32 * i;
            orow[e] = (v[i] - mu) * inv * gamma[e] + beta[e];
        }
    }
}

// ---------------------------------------------------------------------------
extern "C" void kernel_launch(void* const* d_in, const int* in_sizes, int n_in,
                              void* d_out, int out_size)
{
    const float* x     = (const float*)d_in[0];
    const float* W1    = (const float*)d_in[1];
    const float* b1    = (const float*)d_in[2];
    const float* W2    = (const float*)d_in[3];
    const float* b2    = (const float*)d_in[4];
    const float* gamma = (const float*)d_in[5];
    const float* beta  = (const float*)d_in[6];
    float* out = (float*)d_out;

    // Idempotent, host-side only, not a stream op: safe on every call.
    cudaFuncSetAttribute(gemm1_kernel,
                         cudaFuncAttributeMaxDynamicSharedMemorySize, SMEM1);
    cudaFuncSetAttribute(gemm2_fused,
                         cudaFuncAttributeMaxDynamicSharedMemorySize, SMEM2);

    gemm1_kernel<<<dim3(F_ / NT1, S_), 256, SMEM1>>>(x, W1, b1);
    gemm2_fused<<<S_, 512, SMEM2>>>(x, W2, b2, gamma, beta, out);
}